// round 4
// baseline (speedup 1.0000x reference)
#include <cuda_runtime.h>

#define Bsz  512
#define Ssz  2688
#define Fsz  32
#define Hsz  512
#define WEEK 672
#define NCTA 128
#define NTHR 512

#define SA_ROW 68    // floats per sA k-row (64 data + pad), 34 u64
#define SW_ROW 260   // floats per sW k-row (128 gc duplicated = 256 + pad), 130 u64
#define SG_ROW 66    // gate-exchange row stride (floats), 33 u64

typedef unsigned long long u64;

// ---------------- persistent state (device globals; no allocation) ----------
__device__ float d_h0[2][Bsz * Hsz];
__device__ float d_c0[Bsz * Hsz];
__device__ float d_h1[2][Bsz * Hsz];
__device__ float d_c1[Bsz * Hsz];
__device__ float d_bsum0[4 * Hsz];
__device__ float d_bsum1[4 * Hsz];
__device__ unsigned d_bar;

__device__ __forceinline__ float sigm(float x) { return 1.f / (1.f + expf(-x)); }

__device__ __forceinline__ u64 fma2(u64 a, u64 b, u64 c) {
    u64 d;
    asm("fma.rn.f32x2 %0, %1, %2, %3;" : "=l"(d) : "l"(a), "l"(b), "l"(c));
    return d;
}
__device__ __forceinline__ u64 pack2(float lo, float hi) {
    u64 d;
    asm("mov.b64 %0, {%1, %2};" : "=l"(d) : "f"(lo), "f"(hi));
    return d;
}

// XOR swizzle for sA: logical 16B-chunk c (0..15) -> physical chunk c ^ (c>>3).
// Makes both per-thread a-LDS.128 conflict-free across the 8 m-groups.
__device__ __forceinline__ int physf(int m) {       // logical float m (0..63) -> physical float
    int c = m >> 2;
    return ((c ^ (c >> 3)) << 2) + (m & 3);
}

// release/acquire device-wide barrier (128 CTAs, 1 per SM)
__device__ __forceinline__ void gsync() {
    __syncthreads();
    if (threadIdx.x == 0) {
        unsigned old, cur, one = 1u;
        asm volatile("atom.release.gpu.add.u32 %0, [%1], %2;"
                     : "=r"(old) : "l"(&d_bar), "r"(one) : "memory");
        unsigned target = (old / NCTA + 1u) * NCTA;
        do {
            asm volatile("ld.acquire.gpu.u32 %0, [%1];"
                         : "=r"(cur) : "l"(&d_bar) : "memory");
        } while (cur < target);
    }
    __syncthreads();
}

// ---------------- init ------------------------------------------------------
__global__ void init_state(const float* __restrict__ bih0, const float* __restrict__ bhh0,
                           const float* __restrict__ bih1, const float* __restrict__ bhh1) {
    int i = blockIdx.x * blockDim.x + threadIdx.x;
    if (i < Bsz * Hsz) {
        d_h0[0][i] = 0.f; d_h0[1][i] = 0.f; d_c0[i] = 0.f;
        d_h1[0][i] = 0.f; d_h1[1][i] = 0.f; d_c1[i] = 0.f;
    }
    if (i < 4 * Hsz) {
        d_bsum0[i] = bih0[i] + bhh0[i];
        d_bsum1[i] = bih1[i] + bhh1[i];
    }
    if (i == 0) d_bar = 0u;
}

// ---------------- inner product: 8m(4 u64) x 2gc per thread ------------------
template <int KT>
__device__ __forceinline__ void fma_tile(const float* __restrict__ sA,
                                         const float* __restrict__ sW,
                                         int ao0, int ao1, int jg, u64 acc[2][4]) {
    const u64* __restrict__ sA64 = reinterpret_cast<const u64*>(sA);
    const u64* __restrict__ sW64 = reinterpret_cast<const u64*>(sW);
#pragma unroll 8
    for (int k = 0; k < KT; k++) {
        const int ar = k * (SA_ROW / 2);
        u64 av[4];
        av[0] = sA64[ar + ao0];     av[1] = sA64[ar + ao0 + 1];
        av[2] = sA64[ar + ao1];     av[3] = sA64[ar + ao1 + 1];
        u64 wv[2];
        wv[0] = sW64[k * (SW_ROW / 2) + jg * 2];
        wv[1] = sW64[k * (SW_ROW / 2) + jg * 2 + 1];
#pragma unroll
        for (int jj = 0; jj < 2; jj++)
#pragma unroll
            for (int mp = 0; mp < 4; mp++)
                acc[jj][mp] = fma2(av[mp], wv[jj], acc[jj][mp]);
    }
}

// ---------------- the persistent kernel --------------------------------------
__global__ __launch_bounds__(NTHR, 1) void run_all(
    const float* __restrict__ x,
    const float* __restrict__ Wih0, const float* __restrict__ Whh0,
    const float* __restrict__ Wih1, const float* __restrict__ Whh1,
    const float* __restrict__ Wout, const float* __restrict__ bout,
    float* __restrict__ out) {
    __shared__ __align__(16) float sA[33 * SA_ROW];
    __shared__ __align__(16) float sW[33 * SW_ROW];   // reused as gate-exchange sG
    __shared__ float spred[64];

    const int tid = threadIdx.x;
    const int mg = tid & 7;                 // m-group: floats mg*8..mg*8+7
    const int jg = tid >> 3;                // gc pair-group: gc = jg*2 + {0,1}, jg 0..63
    // physical u64 offsets of this thread's two 16B a-chunks
    const int c0 = mg * 2, c1 = mg * 2 + 1;
    const int ao0 = (c0 ^ (c0 >> 3)) * 2;
    const int ao1 = (c1 ^ (c1 >> 3)) * 2;
    const int jt = blockIdx.x & 15, bt = blockIdx.x >> 4;
    const int bn = jt * 32, bm = bt * 64;
    const float bout0 = bout[0];

    float ra[4], rw[8];                     // gmem staging registers

    auto loadA = [&](const float* __restrict__ src, int kc) {
        int b = tid >> 3, kq = tid & 7;     // 4 consecutive k for one batch row
        *reinterpret_cast<float4*>(ra) =
            *reinterpret_cast<const float4*>(&src[(bm + b) * Hsz + kc * 32 + kq * 4]);
    };
    auto loadW = [&](const float* __restrict__ W, int kc) {
        int gc = tid >> 2, kq = tid & 3;    // 8 consecutive k for one gate-col
        int g = gc >> 5, j = gc & 31;
        const float4* p = reinterpret_cast<const float4*>(
            &W[(g * Hsz + bn + j) * Hsz + kc * 32 + kq * 8]);
        *reinterpret_cast<float4*>(&rw[0]) = p[0];
        *reinterpret_cast<float4*>(&rw[4]) = p[1];
    };
    auto storeAW = [&]() {
        int b = tid >> 3, kq = tid & 7;
        int pb = physf(b);
#pragma unroll
        for (int u = 0; u < 4; u++) sA[(kq * 4 + u) * SA_ROW + pb] = ra[u];
        int gc = tid >> 2, kq2 = tid & 3;
        u64* sW64 = reinterpret_cast<u64*>(sW);
#pragma unroll
        for (int u = 0; u < 8; u++)
            sW64[(kq2 * 8 + u) * (SW_ROW / 2) + gc] = pack2(rw[u], rw[u]);
    };

    auto epilogue = [&](const float* __restrict__ bsum, float* __restrict__ cptr,
                        float* __restrict__ hdst, u64 acc[2][4]) {
        __syncthreads();                    // fma done reading sW
        u64* sG64 = reinterpret_cast<u64*>(sW);   // overlay: 128 rows x SG_ROW floats
#pragma unroll
        for (int jj = 0; jj < 2; jj++)
#pragma unroll
            for (int mp = 0; mp < 4; mp++)
                sG64[(jg * 2 + jj) * (SG_ROW / 2) + mg * 4 + mp] = acc[jj][mp];
        __syncthreads();
        float* sG = sW;
        int jl = tid & 31, bq = tid >> 5;   // 16 b-groups of 4
        float bi = bsum[bn + jl];
        float bf = bsum[512 + bn + jl];
        float bg = bsum[1024 + bn + jl];
        float bo = bsum[1536 + bn + jl];
#pragma unroll
        for (int u = 0; u < 4; u++) {
            int b = bq * 4 + u;
            float gi = sG[(jl) * SG_ROW + b];
            float gf = sG[(32 + jl) * SG_ROW + b];
            float gg = sG[(64 + jl) * SG_ROW + b];
            float go = sG[(96 + jl) * SG_ROW + b];
            float iv = sigm(gi + bi);
            float fv = sigm(gf + bf);
            float gv = tanhf(gg + bg);
            float ov = sigm(go + bo);
            int ci = (bm + b) * Hsz + bn + jl;
            float cn = fv * cptr[ci] + iv * gv;
            cptr[ci] = cn;
            hdst[ci] = ov * tanhf(cn);
        }
        __syncthreads();                    // sG free before buffers reused
    };

#pragma unroll 1
    for (int t = 0; t < Ssz; t++) {
        const bool use_orig = (((t / WEEK) & 1) == 0);
        const float* __restrict__ hsrc0 = d_h0[t & 1];
        float* __restrict__ hdst0 = d_h0[(t & 1) ^ 1];
        const float* __restrict__ hsrc1 = d_h1[t & 1];
        float* __restrict__ hdst1 = d_h1[(t & 1) ^ 1];

        // ---- out(t-1) = h1(t-1).Wout + bout ----
        if (t > 0 && (!use_orig || jt == 0)) {
            int b = tid >> 3;
            int k0 = (tid & 7) * 64;
            const float* hp = &hsrc1[(bm + b) * Hsz + k0];
            const float* wp = &Wout[k0];
            float s = 0.f;
#pragma unroll 8
            for (int k = 0; k < 64; k++) s += hp[k] * wp[k];
            s += __shfl_down_sync(0xffffffffu, s, 4);
            s += __shfl_down_sync(0xffffffffu, s, 2);
            s += __shfl_down_sync(0xffffffffu, s, 1);
            if ((tid & 7) == 0) {
                float val = s + bout0;
                spred[b] = val;
                if (jt == 0) out[(bm + b) * Ssz + (t - 1)] = val;
            }
        }
        __syncthreads();

        // ================= layer 0 =================
        u64 acc[2][4];
#pragma unroll
        for (int jj = 0; jj < 2; jj++)
#pragma unroll
            for (int mp = 0; mp < 4; mp++) acc[jj][mp] = 0ull;

        // phase 1: K = 33 input features (feat0 | x[:,1:32] | flag)
        for (int idx = tid; idx < 64 * 33; idx += NTHR) {
            int b = idx / 33, f = idx - b * 33;
            int gb = bm + b;
            float v;
            if (f == 0)      v = use_orig ? x[(gb * Ssz + t) * Fsz] : spred[b];
            else if (f < 32) v = x[(gb * Ssz + t) * Fsz + f];
            else             v = use_orig ? 0.f : 1.f;
            sA[f * SA_ROW + physf(b)] = v;
        }
        for (int idx = tid; idx < 128 * 33; idx += NTHR) {
            int r = idx / 33, f = idx - r * 33;
            float w = Wih0[((r >> 5) * Hsz + bn + (r & 31)) * 33 + f];
            sW[f * SW_ROW + 2 * r]     = w;
            sW[f * SW_ROW + 2 * r + 1] = w;
        }
        loadA(hsrc0, 0); loadW(Whh0, 0);    // prologue for phase 2 (regs only)
        __syncthreads();
        fma_tile<33>(sA, sW, ao0, ao1, jg, acc);

        // phase 2: K = 512 recurrent, register-staged chunks of 32
#pragma unroll 1
        for (int kc = 0; kc < 16; kc++) {
            __syncthreads();
            storeAW();
            __syncthreads();
            if (kc < 15) { loadA(hsrc0, kc + 1); loadW(Whh0, kc + 1); }
            fma_tile<32>(sA, sW, ao0, ao1, jg, acc);
        }
        epilogue(d_bsum0, d_c0, hdst0, acc);
        gsync();

        // ================= layer 1 =================
#pragma unroll
        for (int jj = 0; jj < 2; jj++)
#pragma unroll
            for (int mp = 0; mp < 4; mp++) acc[jj][mp] = 0ull;

        loadA(hdst0, 0); loadW(Wih1, 0);
#pragma unroll 1
        for (int kc = 0; kc < 32; kc++) {
            __syncthreads();
            storeAW();
            __syncthreads();
            int kn = kc + 1;
            if (kn < 32) {
                if (kn < 16) { loadA(hdst0, kn);      loadW(Wih1, kn); }
                else         { loadA(hsrc1, kn - 16); loadW(Whh1, kn - 16); }
            }
            fma_tile<32>(sA, sW, ao0, ao1, jg, acc);
        }
        epilogue(d_bsum1, d_c1, hdst1, acc);
        gsync();
    }

    // ---- final output column ----
    if (jt == 0) {
        const float* __restrict__ hp1 = d_h1[Ssz & 1];
        int b = tid >> 3;
        int k0 = (tid & 7) * 64;
        float s = 0.f;
#pragma unroll 8
        for (int k = 0; k < 64; k++) s += hp1[(bm + b) * Hsz + k0 + k] * Wout[k0 + k];
        s += __shfl_down_sync(0xffffffffu, s, 4);
        s += __shfl_down_sync(0xffffffffu, s, 2);
        s += __shfl_down_sync(0xffffffffu, s, 1);
        if ((tid & 7) == 0) out[(bm + b) * Ssz + (Ssz - 1)] = s + bout0;
    }
}

// ---------------- launch ------------------------------------------------------
extern "C" void kernel_launch(void* const* d_in, const int* in_sizes, int n_in,
                              void* d_out, int out_size) {
    const float* x    = (const float*)d_in[0];
    const float* Wih0 = (const float*)d_in[1];
    const float* Whh0 = (const float*)d_in[2];
    const float* bih0 = (const float*)d_in[3];
    const float* bhh0 = (const float*)d_in[4];
    const float* Wih1 = (const float*)d_in[5];
    const float* Whh1 = (const float*)d_in[6];
    const float* bih1 = (const float*)d_in[7];
    const float* bhh1 = (const float*)d_in[8];
    const float* Wout = (const float*)d_in[9];
    const float* bout = (const float*)d_in[10];
    float* out = (float*)d_out;

    init_state<<<(Bsz * Hsz + 255) / 256, 256>>>(bih0, bhh0, bih1, bhh1);
    run_all<<<NCTA, NTHR>>>(x, Wih0, Whh0, Wih1, Whh1, Wout, bout, out);
}